// round 13
// baseline (speedup 1.0000x reference)
#include <cuda_runtime.h>
#include <cstddef>

// Bidirectional CTC batch cost, prob-domain with exact power-of-two renorm.
// Per CTA (one batch element): warp 0 runs the forward alpha recurrence over
// t=0..255; warp 1 runs the SAME recurrence on the time-reversed,
// state-reversed lattice over t=511..256 (labels reversed). Join at the
// t=255/256 boundary in DOUBLE precision (the forward/backward profiles are
// misaligned by ~175 bits for this data; fp32 junction underflows):
//   L = sum_s' alphaR(128-s') * Atilde(s'),
//   Atilde(s') = a(s') + a(s'-1) + skip(s')*a(s'-2).
// Each warp self-streams its 32 chunks (4KB rows) via cp.async into its own
// 5-slot smem ring. Lane l owns states 4l..4l+3 (lane 31 also state 128/σ128).
// B=512, T=512, C=128, L=64, S=129.

#define CTC_B 512
#define CTC_T 512
#define CTC_C 128
#define CTC_L 64
#define CHUNK 8                     // steps per chunk == renorm period
#define HCHUNK 32                   // chunks per direction (32*8 = 256 steps)
#define SLOTS 5                     // ring slots per warp
#define DIST 4                      // chunk-groups in flight per warp

__global__ __launch_bounds__(64)
void ctc_warp_kernel(const int* __restrict__ y_true,
                     const float* __restrict__ y_pred,
                     float* __restrict__ out)
{
    __shared__ float ring[2][SLOTS * CHUNK * CTC_C];   // 2 x 20 KB
    __shared__ float betaP[CTC_C + 4];                 // [0..128] used
    __shared__ int   kb_s;

    const int b    = blockIdx.x;
    const int tid  = threadIdx.x;
    const int lane = tid & 31;
    const int dir  = tid >> 5;            // 0 = forward, 1 = backward
    const unsigned FULL = 0xffffffffu;
    const float EPSF = 1e-7f;

    // Labels owned by this lane. Forward: states 4l+1 -> y[2l], 4l+3 -> y[2l+1].
    // Backward (reversed ext): sigma=4l+1 -> y[63-2l], sigma=4l+3 -> y[62-2l].
    const int i0 = dir ? (63 - 2 * lane) : (2 * lane);
    const int i1 = dir ? (62 - 2 * lane) : (2 * lane + 1);
    const int c0 = y_true[b * CTC_L + i0];
    const int c1 = y_true[b * CTC_L + i1];
    const int c1_prev = __shfl_up_sync(FULL, c1, 1);
    const bool skip1 = (lane > 0) && (c0 != c1_prev);
    const bool skip3 = (c1 != c0);

    const float* row0 = y_pred + (size_t)b * CTC_T * CTC_C;

    // cp.async one full row (512B) coalesced: lane takes 16B at offset lane*16.
    const unsigned ring_base = (unsigned)__cvta_generic_to_shared(&ring[dir][0]);
    auto load_chunk = [&](int c) {   // direction-local chunk c -> slot c%SLOTS
        if (c < HCHUNK) {
            const int g = dir ? (63 - c) : c;         // global chunk index
            const int sbase = (c % SLOTS) * CHUNK;
            #pragma unroll
            for (int j = 0; j < CHUNK; ++j) {
                unsigned dst = ring_base + (unsigned)(((sbase + j) * CTC_C + lane * 4) * 4);
                const float* src = row0 + (size_t)(g * CHUNK + j) * CTC_C + lane * 4;
                asm volatile("cp.async.cg.shared.global [%0], [%1], 16;\n"
                             :: "r"(dst), "l"(src));
            }
        }
        asm volatile("cp.async.commit_group;\n" ::: "memory");  // commit even if empty
    };

    // Prologue: DIST chunk-groups in flight.
    for (int c = 0; c < DIST; ++c) load_chunk(c);

    // Virtual alpha_{-1} = (2^100, 0, 0, ...) at lane 0; true alpha = stored * 2^K.
    const float TWO100 = __int_as_float((100 + 127) << 23);  // 2^100
    float a0 = (lane == 0) ? TWO100 : 0.0f;
    float a1 = 0.0f, a2 = 0.0f, a3 = 0.0f, a4 = 0.0f;
    float pm1 = 0.0f;     // alpha_{t-1}[4l-1] (prev lane's a3), pipelined shfl
    int   K   = -100;     // integer log2 of the accumulated scale

    for (int c = 0; c < HCHUNK; ++c) {
        // Issue group c+DIST first (writes the slot consumed at iteration c-1,
        // whose LDS reads completed a full iteration ago).
        load_chunk(c + DIST);

        asm volatile("cp.async.wait_group %0;\n" :: "n"(DIST) : "memory");
        __syncwarp();

        const int sbase = (c % SLOTS) * CHUNK;
        #pragma unroll
        for (int j = 0; j < CHUNK; ++j) {
            const int jr = dir ? (CHUNK - 1 - j) : j;   // bwd consumes rows reversed
            const float* rs = &ring[dir][(sbase + jr) * CTC_C];
            const float pb = rs[CTC_C - 1] + EPSF;  // blank (broadcast LDS)
            const float p0 = rs[c0] + EPSF;         // scattered LDS
            const float p1 = rs[c1] + EPSF;

            // new[s] = p[s] * (a[s] + a[s-1] + skip*a[s-2]); states 4l..4l+3 (+128)
            const float n3 = p1 * ((a2 + (skip3 ? a1 : 0.0f)) + a3);
            const float n2 = pb * (a1 + a2);
            const float sh = __shfl_up_sync(FULL, n3, 1);
            const float n0 = pb * (a0 + pm1);
            const float n1 = p0 * ((a0 + (skip1 ? pm1 : 0.0f)) + a1);
            const float n4 = (lane == 31) ? pb * (a3 + a4) : 0.0f;

            pm1 = (lane == 0) ? 0.0f : sh;
            a0 = n0; a1 = n1; a2 = n2; a3 = n3; a4 = n4;
        }

        // Exact renorm: warp max (redux on bits — order-preserving for >=0),
        // round down to 2^k, rescale so max sits in [2^100, 2^101). Scale is an
        // exact power of two tracked in integer K (zero rounding added).
        float m = fmaxf(fmaxf(fmaxf(a0, a1), fmaxf(a2, a3)), a4);
        m = __uint_as_float(__reduce_max_sync(FULL, __float_as_uint(m)));
        const int k = (int)((__float_as_uint(m) >> 23) & 0xff) - 127;
        K += k - 100;
        const float s1 = __int_as_float((127 - k) << 23);  // 2^-k (exact)
        a0 = a0 * s1 * TWO100;
        a1 = a1 * s1 * TWO100;
        a2 = a2 * s1 * TWO100;
        a3 = a3 * s1 * TWO100;
        a4 = a4 * s1 * TWO100;
        pm1 = pm1 * s1 * TWO100;
    }

    // ───────── Junction at t = 255/256 (double precision) ─────────
    if (dir == 1) {
        // Backward warp: publish alphaR. sigma = 4l+k maps to s = 128-(4l+k).
        const int s0 = 128 - 4 * lane;
        betaP[s0]     = a0;
        betaP[s0 - 1] = a1;
        betaP[s0 - 2] = a2;
        betaP[s0 - 3] = a3;
        if (lane == 31) { betaP[0] = a4; kb_s = K; }   // sigma=128 -> s=0
    }
    __syncthreads();

    if (dir == 0) {
        // Atilde(s') = a(s') + a(s'-1) + skip(s')*a(s'-2): one transition step
        // with p==1. pm1 already holds alpha_255[4l-1] (rescaled by renorm).
        // Double precision: stored values are parked near 2^100 per side; the
        // fwd/bwd profiles misalign by up to ~250 bits at the joint peak, far
        // beyond fp32 product range but trivially inside double range.
        const double A0 = (double)a0 + (double)pm1;
        const double A1 = ((double)a0 + (skip1 ? (double)pm1 : 0.0)) + (double)a1;
        const double A2 = (double)a1 + (double)a2;
        const double A3 = ((double)a2 + (skip3 ? (double)a1 : 0.0)) + (double)a3;

        const int s = 4 * lane;
        double t = A0 * (double)betaP[s]     + A1 * (double)betaP[s + 1]
                 + A2 * (double)betaP[s + 2] + A3 * (double)betaP[s + 3];
        if (lane == 31) t += ((double)a3 + (double)a4) * (double)betaP[128];  // s'=128

        #pragma unroll
        for (int o = 16; o; o >>= 1) t += __shfl_xor_sync(FULL, t, o);

        // L = t * 2^(K_f + K_b)
        if (lane == 0) {
            out[b] = (float)(-(log(t) +
                       (double)(K + kb_s) * 0.6931471805599453));
        }
    }
}

extern "C" void kernel_launch(void* const* d_in, const int* in_sizes, int n_in,
                              void* d_out, int out_size)
{
    // Resolve inputs by size (y_true: 512*64 int32, y_pred: 512*512*128 float32).
    const void* p0 = d_in[0];
    const void* p1 = d_in[1];
    const int* y_true;
    const float* y_pred;
    if (in_sizes[0] == CTC_B * CTC_L) {
        y_true = (const int*)p0;
        y_pred = (const float*)p1;
    } else {
        y_true = (const int*)p1;
        y_pred = (const float*)p0;
    }
    float* out = (float*)d_out;

    ctc_warp_kernel<<<CTC_B, 64>>>(y_true, y_pred, out);
}